// round 1
// baseline (speedup 1.0000x reference)
#include <cuda_runtime.h>

#define SEQ    4096
#define BATCH  16
#define HIDDEN 512

// Scratch (no allocations allowed) — all re-written every launch.
__device__ float g_dec[BATCH * HIDDEN];   // decoder features [b][h]
__device__ float g_w[BATCH * SEQ];        // unnormalized masked attention weights
__device__ float g_Z[BATCH];              // per-batch normalizer
__device__ float g_ctx[BATCH * HIDDEN];   // context accumulator (atomics) — zeroed in k0

// ---------------------------------------------------------------------------
// K0: decoder_features[b,k] = dot(x[b,:], W[k,:]) + bias[k]; also zero g_ctx.
// 16 blocks (one per b), 512 threads (16 warps). Warp-per-output-row dot.
// ---------------------------------------------------------------------------
__global__ void k0_dec(const float* __restrict__ x, const float* __restrict__ W,
                       const float* __restrict__ bias) {
    int b   = blockIdx.x;
    int tid = threadIdx.x;             // 512
    __shared__ float xs[HIDDEN];
    xs[tid] = x[b * HIDDEN + tid];
    g_ctx[b * HIDDEN + tid] = 0.0f;
    __syncthreads();

    int warp = tid >> 5, lane = tid & 31;
    for (int k = warp; k < HIDDEN; k += 16) {
        const float4* Wr = reinterpret_cast<const float4*>(W + (size_t)k * HIDDEN);
        float acc = 0.0f;
#pragma unroll
        for (int j = 0; j < 4; ++j) {
            int idx = lane + j * 32;            // 0..127 float4s
            float4 wv = Wr[idx];
            int h = idx * 4;
            acc += wv.x * xs[h] + wv.y * xs[h + 1] + wv.z * xs[h + 2] + wv.w * xs[h + 3];
        }
#pragma unroll
        for (int off = 16; off; off >>= 1) acc += __shfl_down_sync(0xffffffffu, acc, off);
        if (lane == 0) g_dec[b * HIDDEN + k] = acc + bias[k];
    }
}

// ---------------------------------------------------------------------------
// K1: scores + exp + new_scores_sum + unnormalized weights.
// Grid: 2048 blocks = 16 b * 128 s-groups. Block: 256 threads (8 warps),
// each warp handles 4 consecutive s rows -> 32 s per block.
// ---------------------------------------------------------------------------
__global__ void k1_scores(const float* __restrict__ encf,
                          const float* __restrict__ mask,
                          const float* __restrict__ tss,
                          const float* __restrict__ v,
                          float* __restrict__ out_newsum) {
    int b     = blockIdx.x >> 7;          // 128 blocks per b
    int sbase = (blockIdx.x & 127) * 32;
    int tid   = threadIdx.x;              // 256

    __shared__ float ds[HIDDEN];
    __shared__ float vs[HIDDEN];
    ds[tid]       = g_dec[b * HIDDEN + tid];
    ds[tid + 256] = g_dec[b * HIDDEN + tid + 256];
    vs[tid]       = v[tid];
    vs[tid + 256] = v[tid + 256];
    __syncthreads();

    int warp = tid >> 5, lane = tid & 31;
#pragma unroll
    for (int i = 0; i < 4; ++i) {
        int s = sbase + warp * 4 + i;
        const float4* row =
            reinterpret_cast<const float4*>(encf + ((size_t)s * BATCH + b) * HIDDEN);
        float acc = 0.0f;
#pragma unroll
        for (int j = 0; j < 4; ++j) {
            int idx = lane + j * 32;
            float4 ev = row[idx];
            int h = idx * 4;
            acc += tanhf(ds[h]     + ev.x) * vs[h];
            acc += tanhf(ds[h + 1] + ev.y) * vs[h + 1];
            acc += tanhf(ds[h + 2] + ev.z) * vs[h + 2];
            acc += tanhf(ds[h + 3] + ev.w) * vs[h + 3];
        }
#pragma unroll
        for (int off = 16; off; off >>= 1) acc += __shfl_down_sync(0xffffffffu, acc, off);
        if (lane == 0) {
            float e = expf(acc);
            float t = tss[b * SEQ + s];
            out_newsum[b * SEQ + s] = e + t;                 // new_scores_sum
            g_w[b * SEQ + s] = mask[b * SEQ + s] * e / t;    // unnormalized attention
        }
    }
}

// ---------------------------------------------------------------------------
// K2: Z[b] = sum_s w[b,s]. 16 blocks x 256 threads.
// ---------------------------------------------------------------------------
__global__ void k2_Z() {
    int b = blockIdx.x, tid = threadIdx.x;
    float acc = 0.0f;
    for (int s = tid; s < SEQ; s += 256) acc += g_w[b * SEQ + s];
    __shared__ float sm[256];
    sm[tid] = acc;
    __syncthreads();
    for (int off = 128; off; off >>= 1) {
        if (tid < off) sm[tid] += sm[tid + off];
        __syncthreads();
    }
    if (tid == 0) g_Z[b] = sm[0];
}

// ---------------------------------------------------------------------------
// K3: context accumulation: ctx[b,h] += sum_s w[b,s] * enc[s,b,h].
// Grid: 1024 = 16 b * 4 h-chunks(128) * 16 s-chunks(256). 128 threads.
// Each thread owns one h column, accumulates 256 s steps in a register,
// then one atomicAdd.
// ---------------------------------------------------------------------------
__global__ void k3_ctx(const float* __restrict__ enc) {
    int bid = blockIdx.x;
    int sc  = bid & 15;
    int hc  = (bid >> 4) & 3;
    int b   = bid >> 6;
    int tid = threadIdx.x;                 // 128
    int h   = hc * 128 + tid;

    const float* base = enc + (size_t)b * HIDDEN + h;
    const float* wrow = g_w + b * SEQ + sc * 256;
    size_t stride = (size_t)BATCH * HIDDEN;
    size_t off = (size_t)(sc * 256) * stride;

    float acc = 0.0f;
#pragma unroll 4
    for (int i = 0; i < 256; ++i) {
        acc += wrow[i] * __ldg(base + off + (size_t)i * stride);
    }
    atomicAdd(&g_ctx[b * HIDDEN + h], acc);
}

// ---------------------------------------------------------------------------
// K4: finalize: context/Z into out[0:8192), attention = w/Z into out[8192:73728).
// ---------------------------------------------------------------------------
__global__ void k4_final(float* __restrict__ out) {
    int i = blockIdx.x * 256 + threadIdx.x;     // 0..65535
    if (i < BATCH * HIDDEN) {
        int b = i >> 9;
        out[i] = g_ctx[i] / g_Z[b];
    }
    if (i < BATCH * SEQ) {
        int b = i >> 12;
        out[BATCH * HIDDEN + i] = g_w[i] / g_Z[b];
    }
}

// ---------------------------------------------------------------------------
extern "C" void kernel_launch(void* const* d_in, const int* in_sizes, int n_in,
                              void* d_out, int out_size) {
    const float* x    = (const float*)d_in[0];  // outputs_hidden [1,16,512]
    const float* enc  = (const float*)d_in[1];  // encoder_out [4096,16,512]
    const float* encf = (const float*)d_in[2];  // encoder_features [4096,16,512]
    const float* mask = (const float*)d_in[3];  // encoder_mask [16,1,4096]
    const float* tss  = (const float*)d_in[4];  // temporal_scores_sum [16,1,4096]
    const float* W    = (const float*)d_in[5];  // W_feat [512,512]
    const float* bias = (const float*)d_in[6];  // b_feat [512]
    const float* v    = (const float*)d_in[7];  // v_attn [512]

    float* out        = (float*)d_out;
    float* out_newsum = out + BATCH * HIDDEN + BATCH * SEQ;  // third output

    k0_dec   <<<16,   512>>>(x, W, bias);
    k1_scores<<<2048, 256>>>(encf, mask, tss, v, out_newsum);
    k2_Z     <<<16,   256>>>();
    k3_ctx   <<<1024, 128>>>(enc);
    k4_final <<<256,  256>>>(out);
}

// round 2
// speedup vs baseline: 1.5278x; 1.5278x over previous
#include <cuda_runtime.h>

#define SEQ    4096
#define BATCH  16
#define HIDDEN 512
#define SCH    64          // s-chunks in k3
#define SPC    (SEQ/SCH)   // 64 s per chunk

// Scratch (no allocations allowed) — all fully re-written every launch.
__device__ float g_dec[BATCH * HIDDEN];          // decoder features [b][h]
__device__ float g_w[BATCH * SEQ];               // unnormalized masked attention weights
__device__ float g_Z[BATCH];                     // per-batch normalizer
__device__ float g_part[SCH * BATCH * HIDDEN];   // k3 partial sums (deterministic reduce)

__device__ __forceinline__ float tanh_fast(float x) {
    float y;
    asm("tanh.approx.f32 %0, %1;" : "=f"(y) : "f"(x));
    return y;
}

// ---------------------------------------------------------------------------
// K0: decoder_features[b,k] = dot(x[b,:], W[k,:]) + bias[k].
// Grid 128 = 16 b * 8 row-chunks of 64. Block 256 (8 warps), warp handles 8 rows.
// ---------------------------------------------------------------------------
__global__ void k0_dec(const float* __restrict__ x, const float* __restrict__ W,
                       const float* __restrict__ bias) {
    int b     = blockIdx.x >> 3;
    int chunk = blockIdx.x & 7;
    int tid   = threadIdx.x;               // 256
    __shared__ float xs[HIDDEN];
    xs[tid]       = x[b * HIDDEN + tid];
    xs[tid + 256] = x[b * HIDDEN + tid + 256];
    __syncthreads();

    int warp = tid >> 5, lane = tid & 31;
#pragma unroll
    for (int r = 0; r < 8; ++r) {
        int k = chunk * 64 + warp * 8 + r;
        const float4* Wr = reinterpret_cast<const float4*>(W + (size_t)k * HIDDEN);
        float acc = 0.0f;
#pragma unroll
        for (int j = 0; j < 4; ++j) {
            int idx = lane + j * 32;
            float4 wv = Wr[idx];
            int h = idx * 4;
            acc += wv.x * xs[h] + wv.y * xs[h + 1] + wv.z * xs[h + 2] + wv.w * xs[h + 3];
        }
#pragma unroll
        for (int off = 16; off; off >>= 1) acc += __shfl_down_sync(0xffffffffu, acc, off);
        if (lane == 0) g_dec[b * HIDDEN + k] = acc + bias[k];
    }
}

// ---------------------------------------------------------------------------
// K1: scores + exp + new_scores_sum + unnormalized weights.
// Grid: 2048 = 16 b * 128 s-groups of 32. Block 256 (8 warps), warp owns 4 rows.
// All 16 float4 row-loads issued before compute (8 KB in flight per warp).
// ---------------------------------------------------------------------------
__global__ void k1_scores(const float* __restrict__ encf,
                          const float* __restrict__ mask,
                          const float* __restrict__ tss,
                          const float* __restrict__ v,
                          float* __restrict__ out_newsum) {
    int b     = blockIdx.x >> 7;
    int sbase = (blockIdx.x & 127) * 32;
    int tid   = threadIdx.x;               // 256

    __shared__ float ds[HIDDEN];
    __shared__ float vs[HIDDEN];
    ds[tid]       = g_dec[b * HIDDEN + tid];
    ds[tid + 256] = g_dec[b * HIDDEN + tid + 256];
    vs[tid]       = v[tid];
    vs[tid + 256] = v[tid + 256];
    __syncthreads();

    int warp = tid >> 5, lane = tid & 31;
    int s0 = sbase + warp * 4;

    // Batch-load all 4 rows x 4 float4 per lane.
    float4 ev[4][4];
#pragma unroll
    for (int i = 0; i < 4; ++i) {
        const float4* row =
            reinterpret_cast<const float4*>(encf + ((size_t)(s0 + i) * BATCH + b) * HIDDEN);
#pragma unroll
        for (int j = 0; j < 4; ++j) ev[i][j] = row[lane + j * 32];
    }

    float acc[4] = {0.f, 0.f, 0.f, 0.f};
#pragma unroll
    for (int i = 0; i < 4; ++i) {
#pragma unroll
        for (int j = 0; j < 4; ++j) {
            int h = (lane + j * 32) * 4;
            acc[i] += tanh_fast(ds[h]     + ev[i][j].x) * vs[h];
            acc[i] += tanh_fast(ds[h + 1] + ev[i][j].y) * vs[h + 1];
            acc[i] += tanh_fast(ds[h + 2] + ev[i][j].z) * vs[h + 2];
            acc[i] += tanh_fast(ds[h + 3] + ev[i][j].w) * vs[h + 3];
        }
    }
#pragma unroll
    for (int i = 0; i < 4; ++i) {
#pragma unroll
        for (int off = 16; off; off >>= 1)
            acc[i] += __shfl_down_sync(0xffffffffu, acc[i], off);
        if (lane == 0) {
            int s = s0 + i;
            float e = expf(acc[i]);
            float t = tss[b * SEQ + s];
            out_newsum[b * SEQ + s] = e + t;
            g_w[b * SEQ + s] = mask[b * SEQ + s] * e / t;
        }
    }
}

// ---------------------------------------------------------------------------
// K2: Z[b] = sum_s w[b,s]. 16 blocks x 256 threads. Deterministic.
// ---------------------------------------------------------------------------
__global__ void k2_Z() {
    int b = blockIdx.x, tid = threadIdx.x;
    float acc = 0.0f;
    for (int s = tid; s < SEQ; s += 256) acc += g_w[b * SEQ + s];
    __shared__ float sm[256];
    sm[tid] = acc;
    __syncthreads();
    for (int off = 128; off; off >>= 1) {
        if (tid < off) sm[tid] += sm[tid + off];
        __syncthreads();
    }
    if (tid == 0) g_Z[b] = sm[0];
}

// ---------------------------------------------------------------------------
// K3: partial context: part[sc,b,h] = sum_{s in chunk} w[b,s] * enc[s,b,h].
// Grid: 1024 = 16 b * 64 s-chunks of 64. Block 128 threads; thread owns one
// float4 h-slot (full HIDDEN covered). Unroll 8 -> 4 KB in flight per warp.
// ---------------------------------------------------------------------------
__global__ void k3_ctx(const float* __restrict__ enc) {
    int bid = blockIdx.x;
    int sc  = bid & (SCH - 1);
    int b   = bid >> 6;                    // SCH=64
    int tid = threadIdx.x;                 // 128, float4 index over h

    __shared__ float ws[SPC];
    if (tid < SPC) ws[tid] = g_w[b * SEQ + sc * SPC + tid];
    __syncthreads();

    const float4* p = reinterpret_cast<const float4*>(enc)
                    + ((size_t)(sc * SPC) * BATCH + b) * (HIDDEN / 4) + tid;
    const size_t stride = (size_t)BATCH * (HIDDEN / 4);    // float4s per s-step

    float4 acc = make_float4(0.f, 0.f, 0.f, 0.f);
#pragma unroll 8
    for (int i = 0; i < SPC; ++i) {
        float  w = ws[i];
        float4 e = __ldg(p + (size_t)i * stride);
        acc.x += w * e.x; acc.y += w * e.y; acc.z += w * e.z; acc.w += w * e.w;
    }
    reinterpret_cast<float4*>(g_part)[((size_t)sc * BATCH + b) * (HIDDEN / 4) + tid] = acc;
}

// ---------------------------------------------------------------------------
// K4: finalize. ctx[b,h] = (sum_sc part)/Z  -> out[0:8192)
//               attention = w/Z             -> out[8192:73728)
// ---------------------------------------------------------------------------
__global__ void k4_final(float* __restrict__ out) {
    int i = blockIdx.x * 256 + threadIdx.x;     // 0..65535
    if (i < BATCH * HIDDEN) {
        int b = i >> 9;
        float acc = 0.0f;
#pragma unroll 8
        for (int sc = 0; sc < SCH; ++sc)
            acc += g_part[(size_t)sc * BATCH * HIDDEN + i];
        out[i] = acc / g_Z[b];
    }
    if (i < BATCH * SEQ) {
        int b = i >> 12;
        out[BATCH * HIDDEN + i] = g_w[i] / g_Z[b];
    }
}

// ---------------------------------------------------------------------------
extern "C" void kernel_launch(void* const* d_in, const int* in_sizes, int n_in,
                              void* d_out, int out_size) {
    const float* x    = (const float*)d_in[0];  // outputs_hidden [1,16,512]
    const float* enc  = (const float*)d_in[1];  // encoder_out [4096,16,512]
    const float* encf = (const float*)d_in[2];  // encoder_features [4096,16,512]
    const float* mask = (const float*)d_in[3];  // encoder_mask [16,1,4096]
    const float* tss  = (const float*)d_in[4];  // temporal_scores_sum [16,1,4096]
    const float* W    = (const float*)d_in[5];  // W_feat [512,512]
    const float* bias = (const float*)d_in[6];  // b_feat [512]
    const float* v    = (const float*)d_in[7];  // v_attn [512]

    float* out        = (float*)d_out;
    float* out_newsum = out + BATCH * HIDDEN + BATCH * SEQ;  // third output

    k0_dec   <<<128,  256>>>(x, W, bias);
    k1_scores<<<2048, 256>>>(encf, mask, tss, v, out_newsum);
    k2_Z     <<<16,   256>>>();
    k3_ctx   <<<1024, 128>>>(enc);
    k4_final <<<256,  256>>>(out);
}